// round 5
// baseline (speedup 1.0000x reference)
#include <cuda_runtime.h>
#include <cstdint>

// RoiAlign FPN: B=2, N=1000, CROP=7x7, C=256, levels 256/128/64/32/16 (NHWC f32).
// One 448-thread block per box. Phase 1 (threads 0..48) precomputes the 49 pixel
// params into smem. Phase 2: 7 pixels/iter x 64 float4 channel groups, loads
// software-pipelined (8 LDG.128 in flight/warp). Stores go to a 4-deep smem
// staging ring and are written out with one cp.async.bulk (7KB, contiguous)
// per iteration -- removing all STG traffic from the L1tex/LSU pipe.

#define C4 64  // 256 channels / 4

__global__ __launch_bounds__(448, 2) void roialign_kernel(
    const float* __restrict__ boxes,
    const float* __restrict__ f0, const float* __restrict__ f1,
    const float* __restrict__ f2, const float* __restrict__ f3,
    const float* __restrict__ f4,
    const int*   __restrict__ image_shape,
    float*       __restrict__ out,
    int N)
{
    __shared__ float4 s_a[49];                 // corner indices (int bitcast)
    __shared__ float4 s_b[49];                 // lx, ly, okf, 0
    __shared__ const float4* s_fp;             // selected level base pointer
    __shared__ float4 s_stage[4 * 448];        // 4-deep staging ring, 7KB each

    const int boxg = blockIdx.x;
    const int tid  = threadIdx.x;

    // ---------------- Phase 1: per-pixel params (threads 0..48) --------------
    if (tid < 49) {
        // NOTE: reference unpacks boxes[:,0] as "y1" though setup stacked
        // [x1,y1,x2,y2]; features are square so it's a consistent transpose.
        const float a0 = __ldg(boxes + (size_t)boxg * 4 + 0);
        const float a1 = __ldg(boxes + (size_t)boxg * 4 + 1);
        const float a2 = __ldg(boxes + (size_t)boxg * 4 + 2);
        const float a3 = __ldg(boxes + (size_t)boxg * 4 + 3);

        // lvl = clip(round(log2(sqrt(h*w) / (56/sqrt(area)))), 0, 4)
        const float h     = a3 - a1;
        const float w     = a2 - a0;
        const float area  = (float)(image_shape[0] * image_shape[1]);
        const float denom = 56.0f / sqrtf(area);
        int lvl = (int)rintf(log2f(sqrtf(h * w) / denom));  // round-half-even
        lvl = min(max(lvl, 0), 4);

        const int S = 256 >> lvl;
        const float* feat = (lvl == 0) ? f0 : (lvl == 1) ? f1
                          : (lvl == 2) ? f2 : (lvl == 3) ? f3 : f4;
        if (tid == 0) s_fp = (const float4*)feat;

        const float Hf = (float)(S - 1);
        const int gy = tid / 7;
        const int gx = tid % 7;

        // Exact reference op order: ys = y1*Hf + gy*((y2-y1)*Hf/6)
        const float ys = a0 * Hf + (float)gy * (((a2 - a0) * Hf) / 6.0f);
        const float xs = a1 * Hf + (float)gx * (((a3 - a1) * Hf) / 6.0f);

        const float y0f = floorf(ys);
        const float x0f = floorf(xs);
        const float ly  = ys - y0f;
        const float lx  = xs - x0f;

        const int y0 = (int)fminf(fmaxf(y0f,        0.0f), Hf);
        const int y1 = (int)fminf(fmaxf(y0f + 1.0f, 0.0f), Hf);
        const int x0 = (int)fminf(fmaxf(x0f,        0.0f), Hf);
        const int x1 = (int)fminf(fmaxf(x0f + 1.0f, 0.0f), Hf);

        const float okf = ((ys >= 0.0f) & (ys <= Hf) &
                           (xs >= 0.0f) & (xs <= Hf)) ? 1.0f : 0.0f;

        const int bS = (boxg / N) * S;
        const int r0 = (bS + y0) * S;
        const int r1 = (bS + y1) * S;
        // flat indices in float4 units (max ~8.4M, int32-safe)
        s_a[tid] = make_float4(__int_as_float((r0 + x0) * C4),
                               __int_as_float((r0 + x1) * C4),
                               __int_as_float((r1 + x0) * C4),
                               __int_as_float((r1 + x1) * C4));
        s_b[tid] = make_float4(lx, ly, okf, 0.0f);
    }
    __syncthreads();

    // ---------------- Phase 2: pipelined gather + lerp + TMA store -----------
    const float4* __restrict__ fp = s_fp;
    const int psub = tid >> 6;        // pixel sub-slot 0..6
    const int c    = tid & 63;        // float4 channel group 0..63

    // byte address of this box's output (contiguous 49KB)
    uint64_t gdst = (uint64_t)(uintptr_t)out + (uint64_t)boxg * 49 * 1024;
    // shared-space 32-bit address of the staging ring
    uint32_t stage_sa;
    asm("{ .reg .u64 t; cvta.to.shared.u64 t, %1; cvt.u32.u64 %0, t; }"
        : "=r"(stage_sa) : "l"(s_stage));

    // Prologue: issue loads for pixel group 0
    int p = psub;
    float4 qa = s_a[p];
    float4 qb = s_b[p];
    float4 v00 = __ldg(fp + __float_as_int(qa.x) + c);
    float4 v01 = __ldg(fp + __float_as_int(qa.y) + c);
    float4 v10 = __ldg(fp + __float_as_int(qa.z) + c);
    float4 v11 = __ldg(fp + __float_as_int(qa.w) + c);

    #pragma unroll
    for (int it = 0; it < 7; ++it) {
        float4 nqa, nqb, n00, n01, n10, n11;
        if (it < 6) {                 // prefetch next pixel group's corners
            const int np = p + 7;
            nqa = s_a[np];
            nqb = s_b[np];
            n00 = __ldg(fp + __float_as_int(nqa.x) + c);
            n01 = __ldg(fp + __float_as_int(nqa.y) + c);
            n10 = __ldg(fp + __float_as_int(nqa.z) + c);
            n11 = __ldg(fp + __float_as_int(nqa.w) + c);
        }

        const float lx = qb.x, ly = qb.y, okf = qb.z;
        float4 val;
        {
            float t, btm;
            t = v00.x + lx * (v01.x - v00.x); btm = v10.x + lx * (v11.x - v10.x);
            val.x = (t + ly * (btm - t)) * okf;
            t = v00.y + lx * (v01.y - v00.y); btm = v10.y + lx * (v11.y - v10.y);
            val.y = (t + ly * (btm - t)) * okf;
            t = v00.z + lx * (v01.z - v00.z); btm = v10.z + lx * (v11.z - v10.z);
            val.z = (t + ly * (btm - t)) * okf;
            t = v00.w + lx * (v01.w - v00.w); btm = v10.w + lx * (v11.w - v10.w);
            val.w = (t + ly * (btm - t)) * okf;
        }
        // stage into ring buffer (it mod 4); layout matches output: tid*16B
        s_stage[(it & 3) * 448 + tid] = val;
        __syncthreads();

        if (tid == 0) {
            asm volatile("fence.proxy.async;" ::: "memory");
            asm volatile(
                "cp.async.bulk.global.shared::cta.bulk_group [%0], [%1], %2;"
                :: "l"(gdst + (uint64_t)it * 7168),
                   "r"(stage_sa + (uint32_t)(it & 3) * 7168),
                   "r"(7168)
                : "memory");
            asm volatile("cp.async.bulk.commit_group;" ::: "memory");
            // keep <=3 groups in flight so buffer (it+1)&3 is free next iter
            asm volatile("cp.async.bulk.wait_group.read 3;" ::: "memory");
        }
        __syncthreads();

        p += 7;
        qa = nqa; qb = nqb;
        v00 = n00; v01 = n01; v10 = n10; v11 = n11;
    }

    // drain: smem must stay valid until the TMA engine finishes reading it;
    // thread 0 holds the block alive until all groups complete.
    if (tid == 0) {
        asm volatile("cp.async.bulk.wait_group.read 0;" ::: "memory");
    }
}

extern "C" void kernel_launch(void* const* d_in, const int* in_sizes, int n_in,
                              void* d_out, int out_size)
{
    const float* boxes = (const float*)d_in[0];
    const float* f0    = (const float*)d_in[1];
    const float* f1    = (const float*)d_in[2];
    const float* f2    = (const float*)d_in[3];
    const float* f3    = (const float*)d_in[4];
    const float* f4    = (const float*)d_in[5];
    const int*   ishp  = (const int*)d_in[6];

    const int BN = in_sizes[0] / 4;                    // B*N boxes
    const int B  = in_sizes[1] / (256 * 256 * 256);    // feat0 = B*256*256*256
    const int N  = BN / B;

    roialign_kernel<<<BN, 448>>>(boxes, f0, f1, f2, f3, f4, ishp,
                                 (float*)d_out, N);
}

// round 6
// speedup vs baseline: 1.5160x; 1.5160x over previous
#include <cuda_runtime.h>

// RoiAlign FPN: B=2, N=1000, CROP=7x7, C=256, levels 256/128/64/32/16 (NHWC f32).
// One 512-thread block per box. Phase 1 (threads 0..48) precomputes the 49 pixel
// params into smem. Phase 2: 4 pixels/iter x 128 float2 channel groups, 13 iters,
// software-pipelined (8 LDG.64 in flight/thread). LDG.64 chosen over LDG.128 to
// cut L1tex within-LDG replay wavefronts (2 lines/load instead of 4).

#define C4 64   // 256 channels / 4 (float4 units used for index math)

__global__ __launch_bounds__(512, 2) void roialign_kernel(
    const float* __restrict__ boxes,
    const float* __restrict__ f0, const float* __restrict__ f1,
    const float* __restrict__ f2, const float* __restrict__ f3,
    const float* __restrict__ f4,
    const int*   __restrict__ image_shape,
    float*       __restrict__ out,
    int N)
{
    __shared__ float4 s_a[49];                 // corner indices (int bitcast, float4 units)
    __shared__ float4 s_b[49];                 // lx, ly, okf, 0
    __shared__ const float2* s_fp;             // selected level base pointer

    const int boxg = blockIdx.x;
    const int tid  = threadIdx.x;

    // ---------------- Phase 1: per-pixel params (threads 0..48) --------------
    if (tid < 49) {
        // NOTE: reference unpacks boxes[:,0] as "y1" though setup stacked
        // [x1,y1,x2,y2]; features are square so it's a consistent transpose.
        const float a0 = __ldg(boxes + (size_t)boxg * 4 + 0);
        const float a1 = __ldg(boxes + (size_t)boxg * 4 + 1);
        const float a2 = __ldg(boxes + (size_t)boxg * 4 + 2);
        const float a3 = __ldg(boxes + (size_t)boxg * 4 + 3);

        // lvl = clip(round(log2(sqrt(h*w) / (56/sqrt(area)))), 0, 4)
        const float h     = a3 - a1;
        const float w     = a2 - a0;
        const float area  = (float)(image_shape[0] * image_shape[1]);
        const float denom = 56.0f / sqrtf(area);
        int lvl = (int)rintf(log2f(sqrtf(h * w) / denom));  // round-half-even
        lvl = min(max(lvl, 0), 4);

        const int S = 256 >> lvl;
        const float* feat = (lvl == 0) ? f0 : (lvl == 1) ? f1
                          : (lvl == 2) ? f2 : (lvl == 3) ? f3 : f4;
        if (tid == 0) s_fp = (const float2*)feat;

        const float Hf = (float)(S - 1);
        const int gy = tid / 7;
        const int gx = tid % 7;

        // Exact reference op order: ys = y1*Hf + gy*((y2-y1)*Hf/6)
        const float ys = a0 * Hf + (float)gy * (((a2 - a0) * Hf) / 6.0f);
        const float xs = a1 * Hf + (float)gx * (((a3 - a1) * Hf) / 6.0f);

        const float y0f = floorf(ys);
        const float x0f = floorf(xs);
        const float ly  = ys - y0f;
        const float lx  = xs - x0f;

        const int y0 = (int)fminf(fmaxf(y0f,        0.0f), Hf);
        const int y1 = (int)fminf(fmaxf(y0f + 1.0f, 0.0f), Hf);
        const int x0 = (int)fminf(fmaxf(x0f,        0.0f), Hf);
        const int x1 = (int)fminf(fmaxf(x0f + 1.0f, 0.0f), Hf);

        const float okf = ((ys >= 0.0f) & (ys <= Hf) &
                           (xs >= 0.0f) & (xs <= Hf)) ? 1.0f : 0.0f;

        const int bS = (boxg / N) * S;
        const int r0 = (bS + y0) * S;
        const int r1 = (bS + y1) * S;
        // flat indices in float4 units (max ~8.4M, int32-safe; x2 for float2)
        s_a[tid] = make_float4(__int_as_float((r0 + x0) * C4),
                               __int_as_float((r0 + x1) * C4),
                               __int_as_float((r1 + x0) * C4),
                               __int_as_float((r1 + x1) * C4));
        s_b[tid] = make_float4(lx, ly, okf, 0.0f);
    }
    __syncthreads();

    // ---------------- Phase 2: pipelined gather + lerp -----------------------
    const float2* __restrict__ fp = s_fp;
    const int c    = tid & 127;       // float2 channel group 0..127
    const int psub = tid >> 7;        // pixel sub-slot 0..3
    float2* __restrict__ out2 = (float2*)out + (long)boxg * 49 * 128 + c;

    // Prologue: issue loads for pixel group 0 (psub 0..3 all valid)
    int p = psub;
    float4 qa = s_a[p];
    float4 qb = s_b[p];
    float2 v00 = __ldg(fp + __float_as_int(qa.x) * 2 + c);
    float2 v01 = __ldg(fp + __float_as_int(qa.y) * 2 + c);
    float2 v10 = __ldg(fp + __float_as_int(qa.z) * 2 + c);
    float2 v11 = __ldg(fp + __float_as_int(qa.w) * 2 + c);

    #pragma unroll
    for (int it = 0; it < 13; ++it) {
        float4 nqa, nqb;
        float2 n00, n01, n10, n11;
        if (it < 12) {                // prefetch next pixel group's corners
            const int np = p + 4;
            const int npc = (np < 49) ? np : 0;   // safe dummy for tail slots
            nqa = s_a[npc];
            nqb = s_b[npc];
            n00 = __ldg(fp + __float_as_int(nqa.x) * 2 + c);
            n01 = __ldg(fp + __float_as_int(nqa.y) * 2 + c);
            n10 = __ldg(fp + __float_as_int(nqa.z) * 2 + c);
            n11 = __ldg(fp + __float_as_int(nqa.w) * 2 + c);
        }

        const float lx = qb.x, ly = qb.y, okf = qb.z;
        float2 val;
        {
            float t, btm;
            t = v00.x + lx * (v01.x - v00.x); btm = v10.x + lx * (v11.x - v10.x);
            val.x = (t + ly * (btm - t)) * okf;
            t = v00.y + lx * (v01.y - v00.y); btm = v10.y + lx * (v11.y - v10.y);
            val.y = (t + ly * (btm - t)) * okf;
        }
        if (p < 49)
            __stwt(out2 + (long)p * 128, val);    // streaming store, no L2 reuse

        p += 4;
        qa = nqa; qb = nqb;
        v00 = n00; v01 = n01; v10 = n10; v11 = n11;
    }
}

extern "C" void kernel_launch(void* const* d_in, const int* in_sizes, int n_in,
                              void* d_out, int out_size)
{
    const float* boxes = (const float*)d_in[0];
    const float* f0    = (const float*)d_in[1];
    const float* f1    = (const float*)d_in[2];
    const float* f2    = (const float*)d_in[3];
    const float* f3    = (const float*)d_in[4];
    const float* f4    = (const float*)d_in[5];
    const int*   ishp  = (const int*)d_in[6];

    const int BN = in_sizes[0] / 4;                    // B*N boxes
    const int B  = in_sizes[1] / (256 * 256 * 256);    // feat0 = B*256*256*256
    const int N  = BN / B;

    roialign_kernel<<<BN, 512>>>(boxes, f0, f1, f2, f3, f4, ishp,
                                 (float*)d_out, N);
}